// round 6
// baseline (speedup 1.0000x reference)
#include <cuda_runtime.h>
#include <cuda_fp16.h>
#include <cstdint>

#define NN 20000
#define EE 320000
#define TE (EE + NN)          // edges + self loops
#define FIN 128
#define HID 64
#define HEADS 8
#define C1 (HEADS * HID)      // 512
#define NBLK ((NN + 255) / 256)   // 79 scan blocks

// ---------------- scratch (static device globals; no allocation) -------------
__device__ int    g_is64;
__device__ int    g_cnt[NN];
__device__ int    g_off[NN + 1];
__device__ int    g_cur[NN];
__device__ int    g_csr[TE];
__device__ int    g_bsum[NBLK];
__device__ __half g_h1[(size_t)NN * C1];      // 20 MB, fp16 features
__device__ float2 g_xp[(size_t)NN * FIN];     // packed (tf32hi, tf32lo) of x
__device__ float2 g_w1p[FIN * C1];            // packed planes of W1
__device__ float  g_as1[NN * HEADS];
__device__ float  g_ad1[NN * HEADS];
__device__ float  g_h2[NN * 2];
__device__ float  g_as2[NN];
__device__ float  g_ad2[NN];

// ---------------- dtype detection for edge_index -----------------------------
__global__ void k_detect(const int* ei) {
    int lane = threadIdx.x;
    int hi = ei[2 * lane + 1];
    unsigned b = __ballot_sync(0xffffffffu, hi == 0);
    if (lane == 0) g_is64 = (b == 0xffffffffu) ? 1 : 0;
}

// ---------------- tf32 pre-split (packed hi/lo), optional g_cnt zeroing ------
__device__ __forceinline__ float tf32hi(float f) {
    uint32_t u;
    asm("cvt.rna.tf32.f32 %0, %1;" : "=r"(u) : "f"(f));
    return __uint_as_float(u);
}

__global__ void k_split(const float* __restrict__ src, float2* __restrict__ dst,
                        int n4, int zero_cnt) {
    int i = blockIdx.x * blockDim.x + threadIdx.x;
    if (zero_cnt && i < NN) g_cnt[i] = 0;
    if (i >= n4) return;
    float4 v = ((const float4*)src)[i];
    float hx = tf32hi(v.x), hy = tf32hi(v.y), hz = tf32hi(v.z), hw = tf32hi(v.w);
    float4 o0 = make_float4(hx, tf32hi(v.x - hx), hy, tf32hi(v.y - hy));
    float4 o1 = make_float4(hz, tf32hi(v.z - hz), hw, tf32hi(v.w - hw));
    ((float4*)dst)[2 * i + 0] = o0;
    ((float4*)dst)[2 * i + 1] = o1;
}

// ---------------- CSR build ---------------------------------------------------
// paired edge processing: 2 edges per thread, vector loads, no straddle
// (EE and TE are even, so a pair is either both real or both self-loop)
__global__ void k_count(const void* ei) {
    int p = blockIdx.x * blockDim.x + threadIdx.x;
    if (p >= TE / 2) return;
    int d0, d1;
    if (2 * p < EE) {
        if (g_is64) {
            longlong2 v = ((const longlong2*)ei)[EE / 2 + p];
            d0 = (int)v.x; d1 = (int)v.y;
        } else {
            int2 v = ((const int2*)ei)[EE / 2 + p];
            d0 = v.x; d1 = v.y;
        }
    } else {
        d0 = 2 * p - EE; d1 = d0 + 1;
    }
    if (d0 == d1) atomicAdd(&g_cnt[d0], 2);
    else { atomicAdd(&g_cnt[d0], 1); atomicAdd(&g_cnt[d1], 1); }
}

__global__ void k_scanA() {
    int t = threadIdx.x, b = blockIdx.x;
    int i = b * 256 + t;
    int v = (i < NN) ? g_cnt[i] : 0;
    int lane = t & 31, wid = t >> 5;
    int incl = v;
    #pragma unroll
    for (int o = 1; o < 32; o <<= 1) {
        int x = __shfl_up_sync(0xffffffffu, incl, o);
        if (lane >= o) incl += x;
    }
    __shared__ int ws[8];
    if (lane == 31) ws[wid] = incl;
    __syncthreads();
    if (t < 8) {
        int wv = ws[t];
        int wincl = wv;
        #pragma unroll
        for (int o = 1; o < 8; o <<= 1) {
            int x = __shfl_up_sync(0x000000ffu, wincl, o);
            if (t >= o) wincl += x;
        }
        ws[t] = wincl - wv;
        if (t == 7) g_bsum[b] = wincl;
    }
    __syncthreads();
    incl += ws[wid];
    if (i < NN) g_off[i + 1] = incl;
}

// scanC: each block directly reduces prior block sums (NBLK=79, cheap)
__global__ void k_scanC() {
    __shared__ int carry_s;
    int t = threadIdx.x, b = blockIdx.x;
    if (t < 32) {
        int c = 0;
        for (int i = t; i < b; i += 32) c += g_bsum[i];
        #pragma unroll
        for (int o = 16; o >= 1; o >>= 1) c += __shfl_xor_sync(0xffffffffu, c, o);
        if (t == 0) carry_s = c;
    }
    __syncthreads();
    if (b == 0 && t == 0) g_off[0] = 0;
    int i = b * 256 + t;
    if (i >= NN) return;
    int off = carry_s + g_off[i + 1];
    g_off[i + 1] = off;
    g_cur[i] = off - g_cnt[i];
}

__global__ void k_scatter(const void* ei) {
    int p = blockIdx.x * blockDim.x + threadIdx.x;
    if (p >= TE / 2) return;
    int s0, s1, d0, d1;
    if (2 * p < EE) {
        if (g_is64) {
            longlong2 sv = ((const longlong2*)ei)[p];
            longlong2 dv = ((const longlong2*)ei)[EE / 2 + p];
            s0 = (int)sv.x; s1 = (int)sv.y;
            d0 = (int)dv.x; d1 = (int)dv.y;
        } else {
            int2 sv = ((const int2*)ei)[p];
            int2 dv = ((const int2*)ei)[EE / 2 + p];
            s0 = sv.x; s1 = sv.y;
            d0 = dv.x; d1 = dv.y;
        }
    } else {
        s0 = d0 = 2 * p - EE;
        s1 = d1 = s0 + 1;
    }
    if (d0 == d1) {
        int pos = atomicAdd(&g_cur[d0], 2);
        g_csr[pos] = s0;
        g_csr[pos + 1] = s1;
    } else {
        g_csr[atomicAdd(&g_cur[d0], 1)] = s0;
        g_csr[atomicAdd(&g_cur[d1], 1)] = s1;
    }
}

// ---------------- tf32 mma ----------------------------------------------------
__device__ __forceinline__ void mma_tf32(float c[4], const uint32_t a[4], const uint32_t b[2]) {
    asm("mma.sync.aligned.m16n8k8.row.col.f32.tf32.tf32.f32 "
        "{%0,%1,%2,%3},{%4,%5,%6,%7},{%8,%9},{%0,%1,%2,%3};"
        : "+f"(c[0]), "+f"(c[1]), "+f"(c[2]), "+f"(c[3])
        : "r"(a[0]), "r"(a[1]), "r"(a[2]), "r"(a[3]), "r"(b[0]), "r"(b[1]));
}

// ---------------- GEMM1: h1 = x @ W1 via 3xTF32 (packed hi/lo planes) --------
// grid (157, 8) ; block 256 = 8 warps (4 m x 2 n); BM=128 BN=64 BK=16
// smem strides (in float2): A=20 -> banks (8*ar+2*ac)%32 distinct per phase;
// B=68 -> banks (8*krow+2*colq)%32 distinct per phase. One LDS.64 per element
// yields both planes.
#define SAS2 20
#define SBS2 68
__global__ void k_gemm1(const float* __restrict__ att_s, const float* __restrict__ att_d) {
    __shared__ __align__(16) float2 sA[128 * SAS2];   // 20.0 KB
    __shared__ __align__(16) float2 sB[16 * SBS2];    // 8.5 KB
    __shared__ float parts[128][2];
    __shared__ float partd[128][2];

    int tid = threadIdx.x;
    int warp = tid >> 5, lane = tid & 31;
    int wm = (warp >> 1) * 32;       // 0,32,64,96
    int wnidx = warp & 1;
    int wn = wnidx * 32;
    int row0 = blockIdx.x * 128;
    int head = blockIdx.y;
    int col0 = head * 64;

    float acc[2][4][4];
    #pragma unroll
    for (int i = 0; i < 2; i++)
        #pragma unroll
        for (int j = 0; j < 4; j++)
            #pragma unroll
            for (int q = 0; q < 4; q++) acc[i][j][q] = 0.f;

    int ar = lane >> 2, ac = lane & 3;

    for (int chunk = 0; chunk < 8; chunk++) {
        int kk = chunk * 16;
        // fill A: 128x16 float2 = 1024 float4 stores, 4 per thread
        #pragma unroll
        for (int r = 0; r < 4; r++) {
            int idx = tid + 256 * r;
            int m = idx >> 3, kq = idx & 7;     // kq indexes pairs of k
            int grow = row0 + m;
            float4 v = make_float4(0.f, 0.f, 0.f, 0.f);
            if (grow < NN)
                v = ((const float4*)g_xp)[((size_t)grow * FIN + kk) / 2 + kq];
            ((float4*)sA)[m * (SAS2 / 2) + kq] = v;
        }
        // fill B: 16x64 float2 = 512 float4 stores, 2 per thread
        #pragma unroll
        for (int r = 0; r < 2; r++) {
            int idx = tid + 256 * r;
            int k = idx >> 5, cq = idx & 31;    // cq indexes pairs of cols
            float4 v = ((const float4*)g_w1p)[((size_t)(kk + k) * C1 + col0) / 2 + cq];
            ((float4*)sB)[k * (SBS2 / 2) + cq] = v;
        }
        __syncthreads();

        #pragma unroll
        for (int ks = 0; ks < 2; ks++) {
            int kb = ks * 8;
            uint32_t ah[2][4], al[2][4];
            #pragma unroll
            for (int mf = 0; mf < 2; mf++) {
                int mb = wm + mf * 16;
                float2 e0 = sA[(mb + ar) * SAS2 + kb + ac];
                float2 e1 = sA[(mb + ar + 8) * SAS2 + kb + ac];
                float2 e2 = sA[(mb + ar) * SAS2 + kb + ac + 4];
                float2 e3 = sA[(mb + ar + 8) * SAS2 + kb + ac + 4];
                ah[mf][0] = __float_as_uint(e0.x); al[mf][0] = __float_as_uint(e0.y);
                ah[mf][1] = __float_as_uint(e1.x); al[mf][1] = __float_as_uint(e1.y);
                ah[mf][2] = __float_as_uint(e2.x); al[mf][2] = __float_as_uint(e2.y);
                ah[mf][3] = __float_as_uint(e3.x); al[mf][3] = __float_as_uint(e3.y);
            }
            uint32_t bh[4][2], bl[4][2];
            #pragma unroll
            for (int nf = 0; nf < 4; nf++) {
                int col = wn + nf * 8 + (lane >> 2);
                int krow = kb + (lane & 3);
                float2 f0 = sB[krow * SBS2 + col];
                float2 f1 = sB[(krow + 4) * SBS2 + col];
                bh[nf][0] = __float_as_uint(f0.x); bl[nf][0] = __float_as_uint(f0.y);
                bh[nf][1] = __float_as_uint(f1.x); bl[nf][1] = __float_as_uint(f1.y);
            }
            #pragma unroll
            for (int mf = 0; mf < 2; mf++)
                #pragma unroll
                for (int nf = 0; nf < 4; nf++) {
                    mma_tf32(acc[mf][nf], ah[mf], bh[nf]);
                    mma_tf32(acc[mf][nf], ah[mf], bl[nf]);
                    mma_tf32(acc[mf][nf], al[mf], bh[nf]);
                }
        }
        __syncthreads();
    }

    // ---- epilogue: store h1 (fp16) + fused attention dots ------------------
    float asv[4][2], adv[4][2];
    #pragma unroll
    for (int nf = 0; nf < 4; nf++) {
        int cb = head * HID + wn + nf * 8 + 2 * (lane & 3);
        asv[nf][0] = att_s[cb];     asv[nf][1] = att_s[cb + 1];
        adv[nf][0] = att_d[cb];     adv[nf][1] = att_d[cb + 1];
    }

    #pragma unroll
    for (int mf = 0; mf < 2; mf++) {
        int rA = row0 + wm + mf * 16 + (lane >> 2);
        int rB = rA + 8;
        float ps0 = 0.f, pd0 = 0.f, ps1 = 0.f, pd1 = 0.f;
        #pragma unroll
        for (int nf = 0; nf < 4; nf++) {
            int cb = col0 + wn + nf * 8 + 2 * (lane & 3);
            if (rA < NN)
                *(__half2*)&g_h1[(size_t)rA * C1 + cb] =
                    __floats2half2_rn(acc[mf][nf][0], acc[mf][nf][1]);
            if (rB < NN)
                *(__half2*)&g_h1[(size_t)rB * C1 + cb] =
                    __floats2half2_rn(acc[mf][nf][2], acc[mf][nf][3]);
            ps0 += acc[mf][nf][0] * asv[nf][0] + acc[mf][nf][1] * asv[nf][1];
            pd0 += acc[mf][nf][0] * adv[nf][0] + acc[mf][nf][1] * adv[nf][1];
            ps1 += acc[mf][nf][2] * asv[nf][0] + acc[mf][nf][3] * asv[nf][1];
            pd1 += acc[mf][nf][2] * adv[nf][0] + acc[mf][nf][3] * adv[nf][1];
        }
        #pragma unroll
        for (int o = 1; o <= 2; o <<= 1) {
            ps0 += __shfl_xor_sync(0xffffffffu, ps0, o);
            pd0 += __shfl_xor_sync(0xffffffffu, pd0, o);
            ps1 += __shfl_xor_sync(0xffffffffu, ps1, o);
            pd1 += __shfl_xor_sync(0xffffffffu, pd1, o);
        }
        if ((lane & 3) == 0) {
            int lr0 = wm + mf * 16 + (lane >> 2);
            parts[lr0][wnidx] = ps0;
            partd[lr0][wnidx] = pd0;
            parts[lr0 + 8][wnidx] = ps1;
            partd[lr0 + 8][wnidx] = pd1;
        }
    }
    __syncthreads();
    if (tid < 128) {
        int grow = row0 + tid;
        if (grow < NN) {
            g_as1[grow * HEADS + head] = parts[tid][0] + parts[tid][1];
            g_ad1[grow * HEADS + head] = partd[tid][0] + partd[tid][1];
        }
    }
}

// ---------------- layer-1 aggregation (fp16 gathers) + fused layer-2 GEMM ----
__device__ __forceinline__ void acc_u4(float* acc, const uint4& u, float w) {
    float2 f0 = __half22float2(*(const __half2*)&u.x);
    float2 f1 = __half22float2(*(const __half2*)&u.y);
    float2 f2 = __half22float2(*(const __half2*)&u.z);
    float2 f3 = __half22float2(*(const __half2*)&u.w);
    acc[0] += w * f0.x; acc[1] += w * f0.y;
    acc[2] += w * f1.x; acc[3] += w * f1.y;
    acc[4] += w * f2.x; acc[5] += w * f2.y;
    acc[6] += w * f3.x; acc[7] += w * f3.y;
}

__global__ void k_agg1(const float* __restrict__ b1, const float* __restrict__ W2,
                       const float* __restrict__ att_s2, const float* __restrict__ att_d2) {
    __shared__ float sW2[C1 * 2];
    __shared__ float sb1[C1];
    int tid = threadIdx.x;
    for (int j = tid; j < C1 * 2; j += 256) sW2[j] = W2[j];
    for (int j = tid; j < C1; j += 256) sb1[j] = b1[j];
    __syncthreads();

    int node = (blockIdx.x * 256 + tid) >> 5;
    if (node >= NN) return;
    int lane = tid & 31;
    int head = lane >> 2;

    int beg = g_off[node], end = g_off[node + 1];
    float adst = (lane < 8) ? g_ad1[node * HEADS + lane] : 0.f;

    float s = 0.f;
    float acc[16];
    #pragma unroll
    for (int j = 0; j < 16; j++) acc[j] = 0.f;

    int e = beg;
    for (; e + 1 < end; e += 2) {
        int s0 = g_csr[e], s1 = g_csr[e + 1];
        float w0h = 0.f, w1h = 0.f;
        if (lane < 8) {
            float al0 = g_as1[s0 * HEADS + lane] + adst;
            float al1 = g_as1[s1 * HEADS + lane] + adst;
            al0 = al0 > 0.f ? al0 : 0.2f * al0;
            al1 = al1 > 0.f ? al1 : 0.2f * al1;
            w0h = __expf(al0);
            w1h = __expf(al1);
            s += w0h + w1h;
        }
        float w0 = __shfl_sync(0xffffffffu, w0h, head);
        float w1 = __shfl_sync(0xffffffffu, w1h, head);
        const uint4* hp0 = (const uint4*)(g_h1 + (size_t)s0 * C1 + lane * 16);
        const uint4* hp1 = (const uint4*)(g_h1 + (size_t)s1 * C1 + lane * 16);
        uint4 u00 = hp0[0], u01 = hp0[1];
        uint4 u10 = hp1[0], u11 = hp1[1];
        acc_u4(acc,     u00, w0);
        acc_u4(acc + 8, u01, w0);
        acc_u4(acc,     u10, w1);
        acc_u4(acc + 8, u11, w1);
    }
    if (e < end) {
        int s0 = g_csr[e];
        float w0h = 0.f;
        if (lane < 8) {
            float al0 = g_as1[s0 * HEADS + lane] + adst;
            al0 = al0 > 0.f ? al0 : 0.2f * al0;
            w0h = __expf(al0);
            s += w0h;
        }
        float w0 = __shfl_sync(0xffffffffu, w0h, head);
        const uint4* hp0 = (const uint4*)(g_h1 + (size_t)s0 * C1 + lane * 16);
        uint4 u00 = hp0[0], u01 = hp0[1];
        acc_u4(acc,     u00, w0);
        acc_u4(acc + 8, u01, w0);
    }

    float inv_h = (lane < 8) ? (1.f / s) : 0.f;
    float inv = __shfl_sync(0xffffffffu, inv_h, head);

    float p0 = 0.f, p1 = 0.f;
    #pragma unroll
    for (int j = 0; j < 16; j++) {
        int ch = lane * 16 + j;
        float o = acc[j] * inv + sb1[ch];
        float he = o > 0.f ? o : expm1f(o);
        p0 += he * sW2[ch * 2 + 0];
        p1 += he * sW2[ch * 2 + 1];
    }
    #pragma unroll
    for (int off = 16; off >= 1; off >>= 1) {
        p0 += __shfl_xor_sync(0xffffffffu, p0, off);
        p1 += __shfl_xor_sync(0xffffffffu, p1, off);
    }
    if (lane == 0) {
        g_h2[node * 2 + 0] = p0;
        g_h2[node * 2 + 1] = p1;
        g_as2[node] = p0 * att_s2[0] + p1 * att_s2[1];
        g_ad2[node] = p0 * att_d2[0] + p1 * att_d2[1];
    }
}

// ---------------- layer-2 aggregation ----------------------------------------
__global__ void k_agg2(const float* __restrict__ b2, float* __restrict__ out) {
    int tid = threadIdx.x;
    int node = (blockIdx.x * 256 + tid) >> 5;
    if (node >= NN) return;
    int lane = tid & 31;

    int beg = g_off[node], end = g_off[node + 1];
    float adst = g_ad2[node];

    float s = 0.f, a0 = 0.f, a1 = 0.f;
    for (int e = beg + lane; e < end; e += 32) {
        int src = g_csr[e];
        float al = g_as2[src] + adst;
        al = al > 0.f ? al : 0.2f * al;
        float w = __expf(al);
        s  += w;
        a0 += w * g_h2[src * 2 + 0];
        a1 += w * g_h2[src * 2 + 1];
    }
    #pragma unroll
    for (int off = 16; off >= 1; off >>= 1) {
        s  += __shfl_xor_sync(0xffffffffu, s,  off);
        a0 += __shfl_xor_sync(0xffffffffu, a0, off);
        a1 += __shfl_xor_sync(0xffffffffu, a1, off);
    }
    if (lane == 0) {
        float inv = 1.f / s;
        out[node * 2 + 0] = a0 * inv + b2[0];
        out[node * 2 + 1] = a1 * inv + b2[1];
    }
}

// ---------------- launch ------------------------------------------------------
extern "C" void kernel_launch(void* const* d_in, const int* in_sizes, int n_in,
                              void* d_out, int out_size) {
    const float* x   = (const float*)d_in[0];
    const void*  ei  = d_in[1];
    const float* W1  = (const float*)d_in[2];
    const float* as1 = (const float*)d_in[3];
    const float* ad1 = (const float*)d_in[4];
    const float* b1  = (const float*)d_in[5];
    const float* W2  = (const float*)d_in[6];
    const float* as2 = (const float*)d_in[7];
    const float* ad2 = (const float*)d_in[8];
    const float* b2  = (const float*)d_in[9];
    float* out = (float*)d_out;

    float2 *xp, *wp;
    cudaGetSymbolAddress((void**)&xp, g_xp);
    cudaGetSymbolAddress((void**)&wp, g_w1p);

    k_detect<<<1, 32>>>((const int*)ei);                                   // 0
    k_split<<<(NN * FIN / 4 + 255) / 256, 256>>>(x, xp, NN * FIN / 4, 1);  // 1 (+zero cnt)
    k_split<<<(FIN * C1 / 4 + 255) / 256, 256>>>(W1, wp, FIN * C1 / 4, 0); // 2
    k_gemm1<<<dim3((NN + 127) / 128, HEADS), 256>>>(as1, ad1);             // 3 <- profiled
    k_count<<<(TE / 2 + 255) / 256, 256>>>(ei);                            // 4
    k_scanA<<<NBLK, 256>>>();                                              // 5
    k_scanC<<<NBLK, 256>>>();                                              // 6
    k_scatter<<<(TE / 2 + 255) / 256, 256>>>(ei);                          // 7
    k_agg1<<<(NN * 32 + 255) / 256, 256>>>(b1, W2, as2, ad2);              // 8
    k_agg2<<<(NN * 32 + 255) / 256, 256>>>(b2, out);                       // 9
}

// round 7
// speedup vs baseline: 1.2232x; 1.2232x over previous
#include <cuda_runtime.h>
#include <cuda_fp16.h>
#include <cstdint>

#define NN 20000
#define EE 320000
#define TE (EE + NN)          // edges + self loops
#define FIN 128
#define HID 64
#define HEADS 8
#define C1 (HEADS * HID)      // 512
#define NBLK ((NN + 255) / 256)   // 79 scan blocks

// ---------------- scratch (static device globals; no allocation) -------------
__device__ int    g_is64;
__device__ int    g_cnt[NN];
__device__ int    g_off[NN + 1];
__device__ int    g_cur[NN];
__device__ int    g_csr[TE];
__device__ int    g_bsum[NBLK];
__device__ __half g_h1[(size_t)NN * C1];      // 20 MB, fp16 features
__device__ __half g_xhp[(size_t)NN * FIN];    // fp16 hi plane of x   [N][128]
__device__ __half g_xlp[(size_t)NN * FIN];    // fp16 lo plane of x
__device__ __half g_wth[C1 * FIN];            // W1^T hi plane        [n][k]
__device__ __half g_wtl[C1 * FIN];            // W1^T lo plane
__device__ float  g_as1[NN * HEADS];
__device__ float  g_ad1[NN * HEADS];
__device__ float  g_h2[NN * 2];
__device__ float  g_as2[NN];
__device__ float  g_ad2[NN];

// ---------------- dtype detection for edge_index -----------------------------
__global__ void k_detect(const int* ei) {
    int lane = threadIdx.x;
    int hi = ei[2 * lane + 1];
    unsigned b = __ballot_sync(0xffffffffu, hi == 0);
    if (lane == 0) g_is64 = (b == 0xffffffffu) ? 1 : 0;
}

// ---------------- fp16 hi/lo splits -------------------------------------------
// x split: planar fp16, row-major [N][128]; also zeroes g_cnt
__global__ void k_split_x(const float* __restrict__ src) {
    int i = blockIdx.x * blockDim.x + threadIdx.x;
    if (i < NN) g_cnt[i] = 0;
    if (i >= NN * FIN / 4) return;
    float4 v = ((const float4*)src)[i];
    __half hx = __float2half_rn(v.x), hy = __float2half_rn(v.y);
    __half hz = __float2half_rn(v.z), hw = __float2half_rn(v.w);
    __half lx = __float2half_rn(v.x - __half2float(hx));
    __half ly = __float2half_rn(v.y - __half2float(hy));
    __half lz = __float2half_rn(v.z - __half2float(hz));
    __half lw = __float2half_rn(v.w - __half2float(hw));
    ((__half2*)g_xhp)[2 * i + 0] = __halves2half2(hx, hy);
    ((__half2*)g_xhp)[2 * i + 1] = __halves2half2(hz, hw);
    ((__half2*)g_xlp)[2 * i + 0] = __halves2half2(lx, ly);
    ((__half2*)g_xlp)[2 * i + 1] = __halves2half2(lz, lw);
}

// W1 split + transpose: W1 is [K=128][C1=512]; planes stored [n][k]
__global__ void k_split_w(const float* __restrict__ W1) {
    int j = blockIdx.x * blockDim.x + threadIdx.x;
    if (j >= FIN * C1) return;
    int k = j / C1, n = j % C1;
    float v = W1[j];
    __half h = __float2half_rn(v);
    __half l = __float2half_rn(v - __half2float(h));
    g_wth[n * FIN + k] = h;
    g_wtl[n * FIN + k] = l;
}

// ---------------- CSR build ---------------------------------------------------
__global__ void k_count(const void* ei) {
    int p = blockIdx.x * blockDim.x + threadIdx.x;
    if (p >= TE / 2) return;
    int d0, d1;
    if (2 * p < EE) {
        if (g_is64) {
            longlong2 v = ((const longlong2*)ei)[EE / 2 + p];
            d0 = (int)v.x; d1 = (int)v.y;
        } else {
            int2 v = ((const int2*)ei)[EE / 2 + p];
            d0 = v.x; d1 = v.y;
        }
    } else {
        d0 = 2 * p - EE; d1 = d0 + 1;
    }
    if (d0 == d1) atomicAdd(&g_cnt[d0], 2);
    else { atomicAdd(&g_cnt[d0], 1); atomicAdd(&g_cnt[d1], 1); }
}

__global__ void k_scanA() {
    int t = threadIdx.x, b = blockIdx.x;
    int i = b * 256 + t;
    int v = (i < NN) ? g_cnt[i] : 0;
    int lane = t & 31, wid = t >> 5;
    int incl = v;
    #pragma unroll
    for (int o = 1; o < 32; o <<= 1) {
        int x = __shfl_up_sync(0xffffffffu, incl, o);
        if (lane >= o) incl += x;
    }
    __shared__ int ws[8];
    if (lane == 31) ws[wid] = incl;
    __syncthreads();
    if (t < 8) {
        int wv = ws[t];
        int wincl = wv;
        #pragma unroll
        for (int o = 1; o < 8; o <<= 1) {
            int x = __shfl_up_sync(0x000000ffu, wincl, o);
            if (t >= o) wincl += x;
        }
        ws[t] = wincl - wv;
        if (t == 7) g_bsum[b] = wincl;
    }
    __syncthreads();
    incl += ws[wid];
    if (i < NN) g_off[i + 1] = incl;
}

__global__ void k_scanC() {
    __shared__ int carry_s;
    int t = threadIdx.x, b = blockIdx.x;
    if (t < 32) {
        int c = 0;
        for (int i = t; i < b; i += 32) c += g_bsum[i];
        #pragma unroll
        for (int o = 16; o >= 1; o >>= 1) c += __shfl_xor_sync(0xffffffffu, c, o);
        if (t == 0) carry_s = c;
    }
    __syncthreads();
    if (b == 0 && t == 0) g_off[0] = 0;
    int i = b * 256 + t;
    if (i >= NN) return;
    int off = carry_s + g_off[i + 1];
    g_off[i + 1] = off;
    g_cur[i] = off - g_cnt[i];
}

__global__ void k_scatter(const void* ei) {
    int p = blockIdx.x * blockDim.x + threadIdx.x;
    if (p >= TE / 2) return;
    int s0, s1, d0, d1;
    if (2 * p < EE) {
        if (g_is64) {
            longlong2 sv = ((const longlong2*)ei)[p];
            longlong2 dv = ((const longlong2*)ei)[EE / 2 + p];
            s0 = (int)sv.x; s1 = (int)sv.y;
            d0 = (int)dv.x; d1 = (int)dv.y;
        } else {
            int2 sv = ((const int2*)ei)[p];
            int2 dv = ((const int2*)ei)[EE / 2 + p];
            s0 = sv.x; s1 = sv.y;
            d0 = dv.x; d1 = dv.y;
        }
    } else {
        s0 = d0 = 2 * p - EE;
        s1 = d1 = s0 + 1;
    }
    if (d0 == d1) {
        int pos = atomicAdd(&g_cur[d0], 2);
        g_csr[pos] = s0;
        g_csr[pos + 1] = s1;
    } else {
        g_csr[atomicAdd(&g_cur[d0], 1)] = s0;
        g_csr[atomicAdd(&g_cur[d1], 1)] = s1;
    }
}

// ---------------- fp16 mma -----------------------------------------------------
__device__ __forceinline__ void mma_f16(float c[4], const uint32_t a[4], const uint32_t b[2]) {
    asm("mma.sync.aligned.m16n8k16.row.col.f32.f16.f16.f32 "
        "{%0,%1,%2,%3},{%4,%5,%6,%7},{%8,%9},{%0,%1,%2,%3};"
        : "+f"(c[0]), "+f"(c[1]), "+f"(c[2]), "+f"(c[3])
        : "r"(a[0]), "r"(a[1]), "r"(a[2]), "r"(a[3]), "r"(b[0]), "r"(b[1]));
}

// ---------------- GEMM1: h1 = x @ W1 via fp16x3 split (m16n8k16) --------------
// grid (157, 8) ; block 256 = 8 warps (4 m x 2 n); BM=128 BN=64 BK=32
// warp tile 32x32 (2 mf x 4 nf). A smem [m][k] stride 40 halfs; B smem [n][k]
// stride 40 halfs -> fragment u32 loads hit 32 distinct banks.
#define SAH 40
#define SBH 40
__global__ void __launch_bounds__(256, 3)
k_gemm1(const float* __restrict__ att_s, const float* __restrict__ att_d) {
    __shared__ __align__(16) __half sAh[128 * SAH];   // 10.0 KB
    __shared__ __align__(16) __half sAl[128 * SAH];
    __shared__ __align__(16) __half sBh[64 * SBH];    // 5.0 KB
    __shared__ __align__(16) __half sBl[64 * SBH];
    __shared__ float parts[128][2];
    __shared__ float partd[128][2];

    int tid = threadIdx.x;
    int warp = tid >> 5, lane = tid & 31;
    int wm = (warp >> 1) * 32;       // 0,32,64,96
    int wnidx = warp & 1;
    int wn = wnidx * 32;
    int row0 = blockIdx.x * 128;
    int head = blockIdx.y;
    int col0 = head * 64;

    float acc[2][4][4];
    #pragma unroll
    for (int i = 0; i < 2; i++)
        #pragma unroll
        for (int j = 0; j < 4; j++)
            #pragma unroll
            for (int q = 0; q < 4; q++) acc[i][j][q] = 0.f;

    int ar = lane >> 2, ac = lane & 3;

    for (int chunk = 0; chunk < 4; chunk++) {
        int kk = chunk * 32;
        // fill A: 128 rows x 32 halfs per plane = 512 uint4 per plane, 2/thread
        #pragma unroll
        for (int r = 0; r < 2; r++) {
            int idx = tid + 256 * r;
            int m = idx >> 2, q = idx & 3;     // q: uint4 (8 halfs) within row
            int grow = row0 + m;
            uint4 vh = make_uint4(0u, 0u, 0u, 0u), vl = vh;
            if (grow < NN) {
                size_t g = (size_t)grow * FIN + kk + q * 8;
                vh = *(const uint4*)&g_xhp[g];
                vl = *(const uint4*)&g_xlp[g];
            }
            *(uint4*)&sAh[m * SAH + q * 8] = vh;
            *(uint4*)&sAl[m * SAH + q * 8] = vl;
        }
        // fill B: 64 n-rows x 32 halfs per plane = 256 uint4 per plane, 1/thread
        {
            int n = tid >> 2, q = tid & 3;
            size_t g = (size_t)(col0 + n) * FIN + kk + q * 8;
            *(uint4*)&sBh[n * SBH + q * 8] = *(const uint4*)&g_wth[g];
            *(uint4*)&sBl[n * SBH + q * 8] = *(const uint4*)&g_wtl[g];
        }
        __syncthreads();

        #pragma unroll
        for (int ks = 0; ks < 2; ks++) {
            int kb = ks * 16;
            uint32_t ah[2][4], al[2][4];
            #pragma unroll
            for (int mf = 0; mf < 2; mf++) {
                int mb = wm + mf * 16;
                int i0 = (mb + ar) * SAH + kb + 2 * ac;
                int i1 = (mb + ar + 8) * SAH + kb + 2 * ac;
                ah[mf][0] = *(const uint32_t*)&sAh[i0];
                ah[mf][1] = *(const uint32_t*)&sAh[i1];
                ah[mf][2] = *(const uint32_t*)&sAh[i0 + 8];
                ah[mf][3] = *(const uint32_t*)&sAh[i1 + 8];
                al[mf][0] = *(const uint32_t*)&sAl[i0];
                al[mf][1] = *(const uint32_t*)&sAl[i1];
                al[mf][2] = *(const uint32_t*)&sAl[i0 + 8];
                al[mf][3] = *(const uint32_t*)&sAl[i1 + 8];
            }
            uint32_t bh[4][2], bl[4][2];
            #pragma unroll
            for (int nf = 0; nf < 4; nf++) {
                int col = wn + nf * 8 + (lane >> 2);
                int i0 = col * SBH + kb + 2 * (lane & 3);
                bh[nf][0] = *(const uint32_t*)&sBh[i0];
                bh[nf][1] = *(const uint32_t*)&sBh[i0 + 8];
                bl[nf][0] = *(const uint32_t*)&sBl[i0];
                bl[nf][1] = *(const uint32_t*)&sBl[i0 + 8];
            }
            #pragma unroll
            for (int mf = 0; mf < 2; mf++)
                #pragma unroll
                for (int nf = 0; nf < 4; nf++) {
                    mma_f16(acc[mf][nf], ah[mf], bh[nf]);
                    mma_f16(acc[mf][nf], ah[mf], bl[nf]);
                    mma_f16(acc[mf][nf], al[mf], bh[nf]);
                }
        }
        __syncthreads();
    }

    // ---- epilogue: store h1 (fp16) + fused attention dots ------------------
    float asv[4][2], adv[4][2];
    #pragma unroll
    for (int nf = 0; nf < 4; nf++) {
        int cb = head * HID + wn + nf * 8 + 2 * (lane & 3);
        asv[nf][0] = att_s[cb];     asv[nf][1] = att_s[cb + 1];
        adv[nf][0] = att_d[cb];     adv[nf][1] = att_d[cb + 1];
    }

    #pragma unroll
    for (int mf = 0; mf < 2; mf++) {
        int rA = row0 + wm + mf * 16 + (lane >> 2);
        int rB = rA + 8;
        float ps0 = 0.f, pd0 = 0.f, ps1 = 0.f, pd1 = 0.f;
        #pragma unroll
        for (int nf = 0; nf < 4; nf++) {
            int cb = col0 + wn + nf * 8 + 2 * (lane & 3);
            if (rA < NN)
                *(__half2*)&g_h1[(size_t)rA * C1 + cb] =
                    __floats2half2_rn(acc[mf][nf][0], acc[mf][nf][1]);
            if (rB < NN)
                *(__half2*)&g_h1[(size_t)rB * C1 + cb] =
                    __floats2half2_rn(acc[mf][nf][2], acc[mf][nf][3]);
            ps0 += acc[mf][nf][0] * asv[nf][0] + acc[mf][nf][1] * asv[nf][1];
            pd0 += acc[mf][nf][0] * adv[nf][0] + acc[mf][nf][1] * adv[nf][1];
            ps1 += acc[mf][nf][2] * asv[nf][0] + acc[mf][nf][3] * asv[nf][1];
            pd1 += acc[mf][nf][2] * adv[nf][0] + acc[mf][nf][3] * adv[nf][1];
        }
        #pragma unroll
        for (int o = 1; o <= 2; o <<= 1) {
            ps0 += __shfl_xor_sync(0xffffffffu, ps0, o);
            pd0 += __shfl_xor_sync(0xffffffffu, pd0, o);
            ps1 += __shfl_xor_sync(0xffffffffu, ps1, o);
            pd1 += __shfl_xor_sync(0xffffffffu, pd1, o);
        }
        if ((lane & 3) == 0) {
            int lr0 = wm + mf * 16 + (lane >> 2);
            parts[lr0][wnidx] = ps0;
            partd[lr0][wnidx] = pd0;
            parts[lr0 + 8][wnidx] = ps1;
            partd[lr0 + 8][wnidx] = pd1;
        }
    }
    __syncthreads();
    if (tid < 128) {
        int grow = row0 + tid;
        if (grow < NN) {
            g_as1[grow * HEADS + head] = parts[tid][0] + parts[tid][1];
            g_ad1[grow * HEADS + head] = partd[tid][0] + partd[tid][1];
        }
    }
}

// ---------------- layer-1 aggregation (fp16 gathers) + fused layer-2 GEMM ----
__device__ __forceinline__ void acc_u4(float* acc, const uint4& u, float w) {
    float2 f0 = __half22float2(*(const __half2*)&u.x);
    float2 f1 = __half22float2(*(const __half2*)&u.y);
    float2 f2 = __half22float2(*(const __half2*)&u.z);
    float2 f3 = __half22float2(*(const __half2*)&u.w);
    acc[0] += w * f0.x; acc[1] += w * f0.y;
    acc[2] += w * f1.x; acc[3] += w * f1.y;
    acc[4] += w * f2.x; acc[5] += w * f2.y;
    acc[6] += w * f3.x; acc[7] += w * f3.y;
}

__global__ void k_agg1(const float* __restrict__ b1, const float* __restrict__ W2,
                       const float* __restrict__ att_s2, const float* __restrict__ att_d2) {
    __shared__ float sW2[C1 * 2];
    __shared__ float sb1[C1];
    int tid = threadIdx.x;
    for (int j = tid; j < C1 * 2; j += 256) sW2[j] = W2[j];
    for (int j = tid; j < C1; j += 256) sb1[j] = b1[j];
    __syncthreads();

    int node = (blockIdx.x * 256 + tid) >> 5;
    if (node >= NN) return;
    int lane = tid & 31;
    int head = lane >> 2;

    int beg = g_off[node], end = g_off[node + 1];
    float adst = (lane < 8) ? g_ad1[node * HEADS + lane] : 0.f;

    float s = 0.f;
    float acc[16];
    #pragma unroll
    for (int j = 0; j < 16; j++) acc[j] = 0.f;

    int e = beg;
    for (; e + 1 < end; e += 2) {
        int s0 = g_csr[e], s1 = g_csr[e + 1];
        float w0h = 0.f, w1h = 0.f;
        if (lane < 8) {
            float al0 = g_as1[s0 * HEADS + lane] + adst;
            float al1 = g_as1[s1 * HEADS + lane] + adst;
            al0 = al0 > 0.f ? al0 : 0.2f * al0;
            al1 = al1 > 0.f ? al1 : 0.2f * al1;
            w0h = __expf(al0);
            w1h = __expf(al1);
            s += w0h + w1h;
        }
        float w0 = __shfl_sync(0xffffffffu, w0h, head);
        float w1 = __shfl_sync(0xffffffffu, w1h, head);
        const uint4* hp0 = (const uint4*)(g_h1 + (size_t)s0 * C1 + lane * 16);
        const uint4* hp1 = (const uint4*)(g_h1 + (size_t)s1 * C1 + lane * 16);
        uint4 u00 = hp0[0], u01 = hp0[1];
        uint4 u10 = hp1[0], u11 = hp1[1];
        acc_u4(acc,     u00, w0);
        acc_u4(acc + 8, u01, w0);
        acc_u4(acc,     u10, w1);
        acc_u4(acc + 8, u11, w1);
    }
    if (e < end) {
        int s0 = g_csr[e];
        float w0h = 0.f;
        if (lane < 8) {
            float al0 = g_as1[s0 * HEADS + lane] + adst;
            al0 = al0 > 0.f ? al0 : 0.2f * al0;
            w0h = __expf(al0);
            s += w0h;
        }
        float w0 = __shfl_sync(0xffffffffu, w0h, head);
        const uint4* hp0 = (const uint4*)(g_h1 + (size_t)s0 * C1 + lane * 16);
        uint4 u00 = hp0[0], u01 = hp0[1];
        acc_u4(acc,     u00, w0);
        acc_u4(acc + 8, u01, w0);
    }

    float inv_h = (lane < 8) ? (1.f / s) : 0.f;
    float inv = __shfl_sync(0xffffffffu, inv_h, head);

    float p0 = 0.f, p1 = 0.f;
    #pragma unroll
    for (int j = 0; j < 16; j++) {
        int ch = lane * 16 + j;
        float o = acc[j] * inv + sb1[ch];
        float he = o > 0.f ? o : expm1f(o);
        p0 += he * sW2[ch * 2 + 0];
        p1 += he * sW2[ch * 2 + 1];
    }
    #pragma unroll
    for (int off = 16; off >= 1; off >>= 1) {
        p0 += __shfl_xor_sync(0xffffffffu, p0, off);
        p1 += __shfl_xor_sync(0xffffffffu, p1, off);
    }
    if (lane == 0) {
        g_h2[node * 2 + 0] = p0;
        g_h2[node * 2 + 1] = p1;
        g_as2[node] = p0 * att_s2[0] + p1 * att_s2[1];
        g_ad2[node] = p0 * att_d2[0] + p1 * att_d2[1];
    }
}

// ---------------- layer-2 aggregation ----------------------------------------
__global__ void k_agg2(const float* __restrict__ b2, float* __restrict__ out) {
    int tid = threadIdx.x;
    int node = (blockIdx.x * 256 + tid) >> 5;
    if (node >= NN) return;
    int lane = tid & 31;

    int beg = g_off[node], end = g_off[node + 1];
    float adst = g_ad2[node];

    float s = 0.f, a0 = 0.f, a1 = 0.f;
    for (int e = beg + lane; e < end; e += 32) {
        int src = g_csr[e];
        float al = g_as2[src] + adst;
        al = al > 0.f ? al : 0.2f * al;
        float w = __expf(al);
        s  += w;
        a0 += w * g_h2[src * 2 + 0];
        a1 += w * g_h2[src * 2 + 1];
    }
    #pragma unroll
    for (int off = 16; off >= 1; off >>= 1) {
        s  += __shfl_xor_sync(0xffffffffu, s,  off);
        a0 += __shfl_xor_sync(0xffffffffu, a0, off);
        a1 += __shfl_xor_sync(0xffffffffu, a1, off);
    }
    if (lane == 0) {
        float inv = 1.f / s;
        out[node * 2 + 0] = a0 * inv + b2[0];
        out[node * 2 + 1] = a1 * inv + b2[1];
    }
}

// ---------------- launch ------------------------------------------------------
extern "C" void kernel_launch(void* const* d_in, const int* in_sizes, int n_in,
                              void* d_out, int out_size) {
    const float* x   = (const float*)d_in[0];
    const void*  ei  = d_in[1];
    const float* W1  = (const float*)d_in[2];
    const float* as1 = (const float*)d_in[3];
    const float* ad1 = (const float*)d_in[4];
    const float* b1  = (const float*)d_in[5];
    const float* W2  = (const float*)d_in[6];
    const float* as2 = (const float*)d_in[7];
    const float* ad2 = (const float*)d_in[8];
    const float* b2  = (const float*)d_in[9];
    float* out = (float*)d_out;

    k_detect<<<1, 32>>>((const int*)ei);                                   // 0
    k_split_x<<<(NN * FIN / 4 + 255) / 256, 256>>>(x);                     // 1 (+zero cnt)
    k_split_w<<<(FIN * C1 + 255) / 256, 256>>>(W1);                        // 2
    k_gemm1<<<dim3((NN + 127) / 128, HEADS), 256>>>(as1, ad1);             // 3 <- profiled
    k_count<<<(TE / 2 + 255) / 256, 256>>>(ei);                            // 4
    k_scanA<<<NBLK, 256>>>();                                              // 5
    k_scanC<<<NBLK, 256>>>();                                              // 6
    k_scatter<<<(TE / 2 + 255) / 256, 256>>>(ei);                          // 7
    k_agg1<<<(NN * 32 + 255) / 256, 256>>>(b1, W2, as2, ad2);              // 8
    k_agg2<<<(NN * 32 + 255) / 256, 256>>>(b2, out);                       // 9
}